// round 7
// baseline (speedup 1.0000x reference)
#include <cuda_runtime.h>
#include <cstdint>
#include <math.h>

#define LAYERS 3
#define UNITS  1024
#define BATCH  128
#define TSEQ   256
#define NC     (3*UNITS)      // 3072
#define MXW    (BATCH*TSEQ)   // 32768

// recurrent geometry: grid = 64 u-groups x 2 batch-halves = 128 CTAs (co-resident)
#define UGRP   64
#define UB     16
#define CCOLS  48
#define MROWS  64
#define HUSTR  49
#define EPOCH  (TSEQ + 1)     // flag epoch stride per layer

// ---------------- scratch (static device memory) ----------------
__device__ __align__(128) float g_xw[(size_t)MXW * NC];      // [t][b][3U]
__device__ __align__(128) float g_x [(size_t)MXW * UNITS];   // activations (tf32-rounded)
__device__ __align__(128) float g_Wc[(size_t)LAYERS * UNITS * NC]; // tf32-rounded W
__device__ __align__(128) float g_hT[2][UNITS][BATCH];       // tf32 h, transposed
__device__ __align__(128) float g_hF[BATCH * UNITS];         // full-precision h
__device__ int g_flag[2][UGRP];                              // [half][ugroup]

// ---------------- helpers ----------------
__device__ __forceinline__ float tf32r(float v) {
    unsigned r;
    asm("cvt.rna.tf32.f32 %0, %1;" : "=r"(r) : "f"(v));
    return __uint_as_float(r);
}

__device__ __forceinline__ void mma_tf32(float* c, const unsigned* a, const unsigned* b) {
    asm volatile(
        "mma.sync.aligned.m16n8k8.row.col.f32.tf32.tf32.f32 "
        "{%0,%1,%2,%3}, {%4,%5,%6,%7}, {%8,%9}, {%0,%1,%2,%3};"
        : "+f"(c[0]), "+f"(c[1]), "+f"(c[2]), "+f"(c[3])
        : "r"(a[0]), "r"(a[1]), "r"(a[2]), "r"(a[3]), "r"(b[0]), "r"(b[1]));
}

__device__ __forceinline__ uint32_t smem_u32(const void* p) {
    return (uint32_t)__cvta_generic_to_shared(p);
}
__device__ __forceinline__ void mbar_init(uint32_t m, int cnt) {
    asm volatile("mbarrier.init.shared.b64 [%0], %1;" :: "r"(m), "r"(cnt) : "memory");
}
__device__ __forceinline__ void mbar_expect(uint32_t m, int bytes) {
    asm volatile("mbarrier.arrive.expect_tx.shared.b64 _, [%0], %1;"
                 :: "r"(m), "r"(bytes) : "memory");
}
__device__ __forceinline__ void bulk_g2s(uint32_t dst, const void* src, int bytes,
                                         uint32_t mbar) {
    asm volatile(
        "cp.async.bulk.shared::cta.global.mbarrier::complete_tx::bytes [%0], [%1], %2, [%3];"
        :: "r"(dst), "l"(src), "r"(bytes), "r"(mbar) : "memory");
}
__device__ __forceinline__ void mbar_wait(uint32_t mbar, int parity) {
    asm volatile(
        "{\n\t.reg .pred P1;\n"
        "WAIT_%=:\n\t"
        "mbarrier.try_wait.parity.acquire.cta.shared::cta.b64 P1, [%0], %1, 0x989680;\n\t"
        "@P1 bra.uni DONE_%=;\n\t"
        "bra.uni WAIT_%=;\n\t"
        "DONE_%=:\n\t}"
        :: "r"(mbar), "r"(parity) : "memory");
}

__device__ __forceinline__ int ldacq(const int* p) {
    int v;
    asm volatile("ld.acquire.gpu.global.b32 %0, [%1];" : "=r"(v) : "l"(p));
    return v;
}
__device__ __forceinline__ void strel(int* p, int v) {
    asm volatile("st.release.gpu.global.b32 [%0], %1;" :: "l"(p), "r"(v));
}
// lane-0-only polling; rest of warp waits at syncwarp
__device__ __forceinline__ void wait_flag_w(const int* p, int t, int lane) {
    if (lane == 0) {
        if (ldacq(p) < t) {
            while (ldacq(p) < t) { __nanosleep(20); }
        }
    }
    __syncwarp();
}

// ---------------- conversion kernels (also reset flags each replay) ----------------
__global__ void cvt_weights_kernel(const float* __restrict__ W) {
    if (blockIdx.x == 0 && threadIdx.x < 2 * UGRP)
        ((int*)g_flag)[threadIdx.x] = -1;
    size_t n = (size_t)LAYERS * UNITS * NC;
    for (size_t i = blockIdx.x * (size_t)blockDim.x + threadIdx.x; i < n;
         i += (size_t)gridDim.x * blockDim.x)
        g_Wc[i] = tf32r(W[i]);
}
__global__ void cvt_input_kernel(const float* __restrict__ X) {
    size_t n = (size_t)MXW * UNITS;
    for (size_t i = blockIdx.x * (size_t)blockDim.x + threadIdx.x; i < n;
         i += (size_t)gridDim.x * blockDim.x)
        g_x[i] = tf32r(X[i]);
}

// ---------------- XW GEMM with cp.async.bulk staging ----------------
// A smem [m][36] (rows via 128B bulk ops), B smem [k][136] (rows via 512B bulk ops).
#define BM 128
#define BN 128
#define BK 32
#define XA_STR 36
#define XB_STR 136
#define XA_SZ (BM * XA_STR)          // 4608 floats
#define XB_SZ (BK * XB_STR)          // 4352 floats
#define X_STAGE (XA_SZ + XB_SZ)      // 8960 floats
#define X_BASE 32                    // floats reserved for mbarriers
#define XW_SMEM ((X_BASE + 3 * X_STAGE) * 4)
#define STAGE_BYTES (BM * 128 + BK * 512)   // 32768

__global__ __launch_bounds__(256) void gemm_xw_kernel(const float* __restrict__ A,
                                                      const float* __restrict__ Bw,
                                                      const float* __restrict__ bias) {
    extern __shared__ float smx[];
    float* C = g_xw;

    const int tid = threadIdx.x;
    const int lane = tid & 31, wid = tid >> 5;
    const int gid = lane >> 2, tig = lane & 3;
    const int wm = wid & 3, wn = wid >> 2;
    const int mb = wm * 32, nb = wn * 64;
    const int bm0 = blockIdx.y * BM, bn0 = blockIdx.x * BN;

    const uint32_t smem0 = smem_u32(smx);
    const uint32_t mbar0 = smem0;                 // 3 x 8B mbarriers

    if (tid == 0) {
        mbar_init(mbar0, 1);
        mbar_init(mbar0 + 8, 1);
        mbar_init(mbar0 + 16, 1);
        asm volatile("fence.proxy.async.shared::cta;" ::: "memory");
    }
    __syncthreads();

    // warp-0 stage issuer: 5 bulk ops per lane (4 A-rows + 1 B-row)
    auto issue_stage = [&](int ks) {
        const int s = ks % 3;
        const int k0 = ks * BK;
        const uint32_t mb_ = mbar0 + s * 8;
        if (lane == 0) mbar_expect(mb_, STAGE_BYTES);
        __syncwarp();
        const uint32_t abase = smem0 + (X_BASE + s * X_STAGE) * 4;
        const uint32_t bbase = abase + XA_SZ * 4;
#pragma unroll
        for (int r = 0; r < 4; r++) {
            int row = lane + r * 32;
            bulk_g2s(abase + row * (XA_STR * 4),
                     A + (size_t)(bm0 + row) * UNITS + k0, 128, mb_);
        }
        bulk_g2s(bbase + lane * (XB_STR * 4),
                 Bw + (size_t)(k0 + lane) * NC + bn0, 512, mb_);
    };

    float acc[2][8][4];
#pragma unroll
    for (int i = 0; i < 2; i++)
#pragma unroll
        for (int j = 0; j < 8; j++)
#pragma unroll
            for (int q = 0; q < 4; q++) acc[i][j][q] = 0.f;

    if (wid == 0) {
        issue_stage(0);
        issue_stage(1);
        issue_stage(2);
    }

    const int NIT = UNITS / BK;   // 32
    for (int it = 0; it < NIT; it++) {
        const int s = it % 3;
        mbar_wait(mbar0 + s * 8, (it / 3) & 1);

        const float* As2 = smx + X_BASE + s * X_STAGE;
        const float* Bs2 = As2 + XA_SZ;
#pragma unroll
        for (int kk = 0; kk < BK; kk += 8) {
            unsigned a[2][4], bf[8][2];
#pragma unroll
            for (int mt = 0; mt < 2; mt++) {
                int m = mb + mt * 16 + gid;
                a[mt][0] = __float_as_uint(As2[m * XA_STR + kk + tig]);
                a[mt][1] = __float_as_uint(As2[(m + 8) * XA_STR + kk + tig]);
                a[mt][2] = __float_as_uint(As2[m * XA_STR + kk + tig + 4]);
                a[mt][3] = __float_as_uint(As2[(m + 8) * XA_STR + kk + tig + 4]);
            }
#pragma unroll
            for (int nt = 0; nt < 8; nt++) {
                int n = nb + nt * 8 + gid;
                bf[nt][0] = __float_as_uint(Bs2[(kk + tig) * XB_STR + n]);
                bf[nt][1] = __float_as_uint(Bs2[(kk + tig + 4) * XB_STR + n]);
            }
#pragma unroll
            for (int mt = 0; mt < 2; mt++)
#pragma unroll
                for (int nt = 0; nt < 8; nt++) mma_tf32(acc[mt][nt], a[mt], bf[nt]);
        }
        __syncthreads();   // all readers done with stage s before warp 0 overwrites it
        if (it + 3 < NIT && wid == 0) issue_stage(it + 3);
    }

    // epilogue: + bias, store into [t][b][:] layout
#pragma unroll
    for (int mt = 0; mt < 2; mt++) {
#pragma unroll
        for (int nt = 0; nt < 8; nt++) {
            int m0 = bm0 + mb + mt * 16 + gid;    // row = b*TSEQ + t
            int n  = bn0 + nb + nt * 8 + 2 * tig;
            float bv0 = bias[n], bv1 = bias[n + 1];
            int t0 = m0 & (TSEQ - 1), b0r = m0 >> 8;
            int m1 = m0 + 8;
            int t1 = m1 & (TSEQ - 1), b1r = m1 >> 8;
            size_t r0 = ((size_t)t0 * BATCH + b0r) * NC + n;
            size_t r1 = ((size_t)t1 * BATCH + b1r) * NC + n;
            C[r0]     = acc[mt][nt][0] + bv0;
            C[r0 + 1] = acc[mt][nt][1] + bv1;
            C[r1]     = acc[mt][nt][2] + bv0;
            C[r1 + 1] = acc[mt][nt][3] + bv1;
        }
    }
}

// ---------------- persistent GRU layer kernel (warp-autonomous, epoch flags) ----------------
#define GRU_SMEM ((49152 + 64 * HUSTR + 48 + 8) * 4)

__global__ __launch_bounds__(256, 1)
void gru_layer_kernel(int layer, const float* __restrict__ h0,
                      const float* __restrict__ U_raw,
                      const float* __restrict__ bias1,
                      float* __restrict__ yout, float* __restrict__ out_states,
                      int is_last) {
    extern __shared__ float sm[];
    float2* Up2  = (float2*)sm;                 // [128 k8][6 nt][32 lane]
    float*  HU   = sm + 49152;                  // [64][49]
    float*  sbias = HU + 64 * HUSTR;            // [48]

    const int tid  = threadIdx.x;
    const int lane = tid & 31, wid = tid >> 5;
    const int gid  = lane >> 2, tig = lane & 3;
    const int wm   = wid & 1, wk = wid >> 1;    // m-half, k-quarter
    const int mb   = wm * 32;
    const int kq   = wk * 32;                   // warp's first global k8 index
    const int GQ   = wk * 16;                   // warp's first producer ugroup
    const int cm0  = mb + gid;
    const int cm1  = mb + 16 + gid;
    const int u0   = blockIdx.x * UB;
    const int bh   = blockIdx.y;
    const int b0g  = bh * MROWS;
    const int ep   = layer * EPOCH;             // flag epoch base for this layer

    // --- U slice, fragment-major (once per layer) ---
    const float* Uc = U_raw + (size_t)layer * UNITS * NC;
    for (int i = tid; i < 128 * 6 * 32; i += 256) {
        int l2   = i & 31;
        int nt   = (i >> 5) % 6;
        int k8   = i / (6 * 32);
        int ltig = l2 & 3, lgid = l2 >> 2;
        int col  = nt * 8 + lgid;
        int gate = col >> 4, uu = col & 15;
        size_t cofs = (size_t)gate * UNITS + u0 + uu;
        float v0 = tf32r(Uc[(size_t)(8 * k8 + ltig) * NC + cofs]);
        float v1 = tf32r(Uc[(size_t)(8 * k8 + ltig + 4) * NC + cofs]);
        Up2[i] = make_float2(v0, v1);
    }
    if (tid < CCOLS) {
        int gate = tid >> 4, uu = tid & 15;
        sbias[tid] = bias1[gate * UNITS + u0 + uu];
    }

    const int eb  = b0g + (tid >> 2);
    const int eu4 = (tid & 3) * 4;

    // init h; publish state 0 at epoch base
    {
        float4 hv;
        const float* src = h0 + ((size_t)eb * UNITS + u0 + eu4) * LAYERS + layer;
        hv.x = src[0]; hv.y = src[3]; hv.z = src[6]; hv.w = src[9];
        *(float4*)(g_hF + (size_t)eb * UNITS + u0 + eu4) = hv;
        g_hT[0][u0 + eu4 + 0][eb] = tf32r(hv.x);
        g_hT[0][u0 + eu4 + 1][eb] = tf32r(hv.y);
        g_hT[0][u0 + eu4 + 2][eb] = tf32r(hv.z);
        g_hT[0][u0 + eu4 + 3][eb] = tf32r(hv.w);
    }
    __threadfence();
    __syncthreads();
    if (tid == 0) strel(&g_flag[bh][blockIdx.x], ep);

#define PREFETCH(slot, step) do {                                              \
        const float* rp = hTp + (size_t)((kq + (step)) * 8 + tig) * BATCH;     \
        const float* rp4 = rp + 4 * BATCH;                                     \
        ar[slot][0][0] = __float_as_uint(__ldcg(rp + cm0));                    \
        ar[slot][0][1] = __float_as_uint(__ldcg(rp + cm0 + 8));                \
        ar[slot][1][0] = __float_as_uint(__ldcg(rp + cm1));                    \
        ar[slot][1][1] = __float_as_uint(__ldcg(rp + cm1 + 8));                \
        ar[slot][0][2] = __float_as_uint(__ldcg(rp4 + cm0));                   \
        ar[slot][0][3] = __float_as_uint(__ldcg(rp4 + cm0 + 8));               \
        ar[slot][1][2] = __float_as_uint(__ldcg(rp4 + cm1));                   \
        ar[slot][1][3] = __float_as_uint(__ldcg(rp4 + cm1 + 8));               \
    } while (0)

    for (int t = 0; t < TSEQ; t++) {
        const int rb = t & 1;
        const float* hTp = &g_hT[rb][0][b0g];
        const int wt = ep + t;                  // flag level required this step

        const float* xwrow = g_xw + ((size_t)t * BATCH + eb) * NC + u0 + eu4;
        float4 xz4 = *(const float4*)(xwrow);
        float4 xr4 = *(const float4*)(xwrow + UNITS);
        float4 xh4 = *(const float4*)(xwrow + 2 * UNITS);
        float4 hp4 = *(const float4*)(g_hF + (size_t)eb * UNITS + u0 + eu4);

        float acc[2][6][4];
#pragma unroll
        for (int i = 0; i < 2; i++)
#pragma unroll
            for (int j = 0; j < 6; j++)
#pragma unroll
                for (int q = 0; q < 4; q++) acc[i][j][q] = 0.f;

        unsigned ar[4][2][4];
        wait_flag_w(&g_flag[bh][GQ], wt, lane);
        PREFETCH(0, 0);
        PREFETCH(1, 1);
        wait_flag_w(&g_flag[bh][GQ + 1], wt, lane);
        PREFETCH(2, 2);
        PREFETCH(3, 3);

        for (int s = 0; s < 32; s += 4) {
#pragma unroll
            for (int j = 0; j < 4; j++) {
                const int u = s + j;
                const int gk8 = kq + u;
                float2 bq[6];
#pragma unroll
                for (int nt = 0; nt < 6; nt++) bq[nt] = Up2[(gk8 * 6 + nt) * 32 + lane];
                unsigned bfr[6][2];
#pragma unroll
                for (int nt = 0; nt < 6; nt++) {
                    bfr[nt][0] = __float_as_uint(bq[nt].x);
                    bfr[nt][1] = __float_as_uint(bq[nt].y);
                }
#pragma unroll
                for (int mt = 0; mt < 2; mt++)
#pragma unroll
                    for (int nt = 0; nt < 6; nt++) mma_tf32(acc[mt][nt], ar[j][mt], bfr[nt]);
                if (u < 28) {
                    if ((j & 1) == 0)
                        wait_flag_w(&g_flag[bh][(kq + u + 4) >> 1], wt, lane);
                    PREFETCH(j, u + 4);
                }
            }
        }
        __syncthreads();

        // k-split merge: 4 sequential passes over HU
#pragma unroll
        for (int pass = 0; pass < 4; pass++) {
            if (wk == pass) {
#pragma unroll
                for (int mt = 0; mt < 2; mt++)
#pragma unroll
                    for (int nt = 0; nt < 6; nt++) {
                        int m = mb + mt * 16 + gid;
                        int n = nt * 8 + 2 * tig;
                        if (pass == 0) {
                            HU[m * HUSTR + n]           = acc[mt][nt][0];
                            HU[m * HUSTR + n + 1]       = acc[mt][nt][1];
                            HU[(m + 8) * HUSTR + n]     = acc[mt][nt][2];
                            HU[(m + 8) * HUSTR + n + 1] = acc[mt][nt][3];
                        } else {
                            HU[m * HUSTR + n]           += acc[mt][nt][0];
                            HU[m * HUSTR + n + 1]       += acc[mt][nt][1];
                            HU[(m + 8) * HUSTR + n]     += acc[mt][nt][2];
                            HU[(m + 8) * HUSTR + n + 1] += acc[mt][nt][3];
                        }
                    }
            }
            __syncthreads();
        }

        // gate epilogue
        const int wb = 1 - rb;
        const int m  = tid >> 2;
        float hn4[4];
        const float xz[4] = {xz4.x, xz4.y, xz4.z, xz4.w};
        const float xr[4] = {xr4.x, xr4.y, xr4.z, xr4.w};
        const float xh[4] = {xh4.x, xh4.y, xh4.z, xh4.w};
        const float hp[4] = {hp4.x, hp4.y, hp4.z, hp4.w};
#pragma unroll
        for (int j = 0; j < 4; j++) {
            int uu = eu4 + j;
            float hz = HU[m * HUSTR + uu]          + sbias[uu];
            float hr = HU[m * HUSTR + UB + uu]     + sbias[UB + uu];
            float hh = HU[m * HUSTR + 2 * UB + uu] + sbias[2 * UB + uu];
            float z    = 1.f / (1.f + __expf(-(xz[j] + hz)));
            float rg   = 1.f / (1.f + __expf(-(xr[j] + hr)));
            float hhat = tanhf(xh[j] + rg * hh);
            float hn   = z * hp[j] + (1.f - z) * hhat;
            hn4[j] = hn;
            g_hT[wb][u0 + uu][eb] = tf32r(hn);
        }
        *(float4*)(g_hF + (size_t)eb * UNITS + u0 + eu4) =
            make_float4(hn4[0], hn4[1], hn4[2], hn4[3]);
        size_t yi = ((size_t)eb * TSEQ + t) * UNITS + u0 + eu4;
        if (is_last) {
            *(float4*)(yout + yi) = make_float4(hn4[0], hn4[1], hn4[2], hn4[3]);
        } else {
            *(float4*)(g_x + yi) =
                make_float4(tf32r(hn4[0]), tf32r(hn4[1]), tf32r(hn4[2]), tf32r(hn4[3]));
        }

        __threadfence();
        __syncthreads();
        if (tid == 0) strel(&g_flag[bh][blockIdx.x], ep + t + 1);
    }
#undef PREFETCH

    // final states
    {
        float4 hv = *(const float4*)(g_hF + (size_t)eb * UNITS + u0 + eu4);
        float* d = out_states + ((size_t)eb * UNITS + u0 + eu4) * LAYERS + layer;
        d[0] = hv.x; d[3] = hv.y; d[6] = hv.z; d[9] = hv.w;
    }
}

// ---------------- host launcher ----------------
extern "C" void kernel_launch(void* const* d_in, const int* in_sizes, int n_in,
                              void* d_out, int out_size) {
    (void)in_sizes; (void)n_in; (void)out_size;
    const float* x_in = (const float*)d_in[0];
    const float* h0   = (const float*)d_in[1];
    const float* W    = (const float*)d_in[2];
    const float* U    = (const float*)d_in[3];
    const float* b    = (const float*)d_in[4];
    float* out        = (float*)d_out;
    float* out_states = out + (size_t)MXW * UNITS;

    static float* g_x_ptr = nullptr;
    static float* g_Wc_ptr = nullptr;
    if (!g_x_ptr)  cudaGetSymbolAddress((void**)&g_x_ptr, g_x);
    if (!g_Wc_ptr) cudaGetSymbolAddress((void**)&g_Wc_ptr, g_Wc);

    cudaFuncSetAttribute(gru_layer_kernel,
                         cudaFuncAttributeMaxDynamicSharedMemorySize, GRU_SMEM);
    cudaFuncSetAttribute(gemm_xw_kernel,
                         cudaFuncAttributeMaxDynamicSharedMemorySize, XW_SMEM);

    cvt_weights_kernel<<<4096, 256>>>(W);   // also resets flags each replay
    cvt_input_kernel<<<8192, 256>>>(x_in);

    for (int l = 0; l < LAYERS; l++) {
        gemm_xw_kernel<<<dim3(NC / BN, MXW / BM), 256, XW_SMEM>>>(
            g_x_ptr, g_Wc_ptr + (size_t)l * UNITS * NC, b + (size_t)l * 2 * NC);
        gru_layer_kernel<<<dim3(UGRP, 2), 256, GRU_SMEM>>>(
            l, h0, U, b + (size_t)l * 2 * NC + NC, out, out_states, l == LAYERS - 1);
    }
}

// round 8
// speedup vs baseline: 1.4554x; 1.4554x over previous
#include <cuda_runtime.h>
#include <cstdint>
#include <math.h>

#define LAYERS 3
#define UNITS  1024
#define BATCH  128
#define TSEQ   256
#define NC     (3*UNITS)      // 3072
#define MXW    (BATCH*TSEQ)   // 32768

// recurrent geometry: grid = 64 u-groups x 2 batch-halves = 128 CTAs (co-resident)
#define UGRP   64
#define UB     16
#define CCOLS  48
#define MROWS  64
#define HUSTR  49
#define ARR    256                      // flag arrivals per CTA per state
#define LAYER_EP (ARR * (TSEQ + 1))     // flag epoch stride per layer

// ---------------- scratch (static device memory) ----------------
__device__ __align__(128) float g_xw[(size_t)MXW * NC];      // [t][b][3U]
__device__ __align__(128) float g_x [(size_t)MXW * UNITS];   // activations (tf32-rounded)
__device__ __align__(128) float g_Wc[(size_t)LAYERS * UNITS * NC]; // tf32-rounded W
__device__ __align__(128) float g_hT[2][UNITS][BATCH];       // tf32 h, transposed
__device__ unsigned g_flag[2][UGRP];                         // [half][ugroup]

// ---------------- helpers ----------------
__device__ __forceinline__ float tf32r(float v) {
    unsigned r;
    asm("cvt.rna.tf32.f32 %0, %1;" : "=r"(r) : "f"(v));
    return __uint_as_float(r);
}

__device__ __forceinline__ void mma_tf32(float* c, const unsigned* a, const unsigned* b) {
    asm volatile(
        "mma.sync.aligned.m16n8k8.row.col.f32.tf32.tf32.f32 "
        "{%0,%1,%2,%3}, {%4,%5,%6,%7}, {%8,%9}, {%0,%1,%2,%3};"
        : "+f"(c[0]), "+f"(c[1]), "+f"(c[2]), "+f"(c[3])
        : "r"(a[0]), "r"(a[1]), "r"(a[2]), "r"(a[3]), "r"(b[0]), "r"(b[1]));
}

__device__ __forceinline__ uint32_t smem_u32(const void* p) {
    return (uint32_t)__cvta_generic_to_shared(p);
}
__device__ __forceinline__ void mbar_init(uint32_t m, int cnt) {
    asm volatile("mbarrier.init.shared.b64 [%0], %1;" :: "r"(m), "r"(cnt) : "memory");
}
__device__ __forceinline__ void mbar_expect(uint32_t m, int bytes) {
    asm volatile("mbarrier.arrive.expect_tx.shared.b64 _, [%0], %1;"
                 :: "r"(m), "r"(bytes) : "memory");
}
__device__ __forceinline__ void bulk_g2s(uint32_t dst, const void* src, int bytes,
                                         uint32_t mbar) {
    asm volatile(
        "cp.async.bulk.shared::cta.global.mbarrier::complete_tx::bytes [%0], [%1], %2, [%3];"
        :: "r"(dst), "l"(src), "r"(bytes), "r"(mbar) : "memory");
}
__device__ __forceinline__ void mbar_wait(uint32_t mbar, int parity) {
    asm volatile(
        "{\n\t.reg .pred P1;\n"
        "WAIT_%=:\n\t"
        "mbarrier.try_wait.parity.acquire.cta.shared::cta.b64 P1, [%0], %1, 0x989680;\n\t"
        "@P1 bra.uni DONE_%=;\n\t"
        "bra.uni WAIT_%=;\n\t"
        "DONE_%=:\n\t}"
        :: "r"(mbar), "r"(parity) : "memory");
}

__device__ __forceinline__ unsigned ldacq(const unsigned* p) {
    unsigned v;
    asm volatile("ld.acquire.gpu.global.u32 %0, [%1];" : "=r"(v) : "l"(p));
    return v;
}
__device__ __forceinline__ void red_release(unsigned* p) {
    asm volatile("red.release.gpu.global.add.u32 [%0], 1;" :: "l"(p));
}
__device__ __forceinline__ void wait_flag(const unsigned* p, unsigned thr) {
    while (ldacq(p) < thr) {}
}

// ---------------- conversion kernels (also reset flags each replay) ----------------
__global__ void cvt_weights_kernel(const float* __restrict__ W) {
    if (blockIdx.x == 0 && threadIdx.x < 2 * UGRP)
        ((unsigned*)g_flag)[threadIdx.x] = 0u;
    size_t n = (size_t)LAYERS * UNITS * NC;
    for (size_t i = blockIdx.x * (size_t)blockDim.x + threadIdx.x; i < n;
         i += (size_t)gridDim.x * blockDim.x)
        g_Wc[i] = tf32r(W[i]);
}
__global__ void cvt_input_kernel(const float* __restrict__ X) {
    size_t n = (size_t)MXW * UNITS;
    for (size_t i = blockIdx.x * (size_t)blockDim.x + threadIdx.x; i < n;
         i += (size_t)gridDim.x * blockDim.x)
        g_x[i] = tf32r(X[i]);
}

// ---------------- XW GEMM: 2-stage cp.async.bulk, 2 CTAs/SM ----------------
#define BM 128
#define BN 128
#define BK 32
#define XA_STR 36
#define XB_STR 136
#define XA_SZ (BM * XA_STR)          // 4608 floats
#define XB_SZ (BK * XB_STR)          // 4352 floats
#define X_STAGE (XA_SZ + XB_SZ)      // 8960 floats
#define X_BASE 32
#define XNST 2
#define XW_SMEM ((X_BASE + XNST * X_STAGE) * 4)   // 71808 bytes -> 2 CTAs/SM
#define STAGE_BYTES (BM * 128 + BK * 512)         // 32768

__global__ __launch_bounds__(256, 2) void gemm_xw_kernel(const float* __restrict__ A,
                                                         const float* __restrict__ Bw,
                                                         const float* __restrict__ bias) {
    extern __shared__ float smx[];
    float* C = g_xw;

    const int tid = threadIdx.x;
    const int lane = tid & 31, wid = tid >> 5;
    const int gid = lane >> 2, tig = lane & 3;
    const int wm = wid & 3, wn = wid >> 2;
    const int mb = wm * 32, nb = wn * 64;
    const int bm0 = blockIdx.y * BM, bn0 = blockIdx.x * BN;

    const uint32_t smem0 = smem_u32(smx);
    const uint32_t mbar0 = smem0;                 // 2 x 8B mbarriers

    if (tid == 0) {
        mbar_init(mbar0, 1);
        mbar_init(mbar0 + 8, 1);
        asm volatile("fence.proxy.async.shared::cta;" ::: "memory");
    }
    __syncthreads();

    auto issue_stage = [&](int ks) {
        const int s = ks & 1;
        const int k0 = ks * BK;
        const uint32_t mb_ = mbar0 + s * 8;
        if (lane == 0) mbar_expect(mb_, STAGE_BYTES);
        __syncwarp();
        const uint32_t abase = smem0 + (X_BASE + s * X_STAGE) * 4;
        const uint32_t bbase = abase + XA_SZ * 4;
#pragma unroll
        for (int r = 0; r < 4; r++) {
            int row = lane + r * 32;
            bulk_g2s(abase + row * (XA_STR * 4),
                     A + (size_t)(bm0 + row) * UNITS + k0, 128, mb_);
        }
        bulk_g2s(bbase + lane * (XB_STR * 4),
                 Bw + (size_t)(k0 + lane) * NC + bn0, 512, mb_);
    };

    float acc[2][8][4];
#pragma unroll
    for (int i = 0; i < 2; i++)
#pragma unroll
        for (int j = 0; j < 8; j++)
#pragma unroll
            for (int q = 0; q < 4; q++) acc[i][j][q] = 0.f;

    if (wid == 0) {
        issue_stage(0);
        issue_stage(1);
    }

    const int NIT = UNITS / BK;   // 32
    for (int it = 0; it < NIT; it++) {
        const int s = it & 1;
        mbar_wait(mbar0 + s * 8, (it >> 1) & 1);

        const float* As2 = smx + X_BASE + s * X_STAGE;
        const float* Bs2 = As2 + XA_SZ;
#pragma unroll
        for (int kk = 0; kk < BK; kk += 8) {
            unsigned a[2][4], bf[8][2];
#pragma unroll
            for (int mt = 0; mt < 2; mt++) {
                int m = mb + mt * 16 + gid;
                a[mt][0] = __float_as_uint(As2[m * XA_STR + kk + tig]);
                a[mt][1] = __float_as_uint(As2[(m + 8) * XA_STR + kk + tig]);
                a[mt][2] = __float_as_uint(As2[m * XA_STR + kk + tig + 4]);
                a[mt][3] = __float_as_uint(As2[(m + 8) * XA_STR + kk + tig + 4]);
            }
#pragma unroll
            for (int nt = 0; nt < 8; nt++) {
                int n = nb + nt * 8 + gid;
                bf[nt][0] = __float_as_uint(Bs2[(kk + tig) * XB_STR + n]);
                bf[nt][1] = __float_as_uint(Bs2[(kk + tig + 4) * XB_STR + n]);
            }
#pragma unroll
            for (int mt = 0; mt < 2; mt++)
#pragma unroll
                for (int nt = 0; nt < 8; nt++) mma_tf32(acc[mt][nt], a[mt], bf[nt]);
        }
        __syncthreads();
        if (it + 2 < NIT && wid == 0) issue_stage(it + 2);
    }

#pragma unroll
    for (int mt = 0; mt < 2; mt++) {
#pragma unroll
        for (int nt = 0; nt < 8; nt++) {
            int m0 = bm0 + mb + mt * 16 + gid;    // row = b*TSEQ + t
            int n  = bn0 + nb + nt * 8 + 2 * tig;
            float bv0 = bias[n], bv1 = bias[n + 1];
            int t0 = m0 & (TSEQ - 1), b0r = m0 >> 8;
            int m1 = m0 + 8;
            int t1 = m1 & (TSEQ - 1), b1r = m1 >> 8;
            size_t r0 = ((size_t)t0 * BATCH + b0r) * NC + n;
            size_t r1 = ((size_t)t1 * BATCH + b1r) * NC + n;
            C[r0]     = acc[mt][nt][0] + bv0;
            C[r0 + 1] = acc[mt][nt][1] + bv1;
            C[r1]     = acc[mt][nt][2] + bv0;
            C[r1 + 1] = acc[mt][nt][3] + bv1;
        }
    }
}

// ---------------- persistent GRU layer kernel ----------------
// 8 warps: wm(2) x wk(4), warp tile m32 x n48, k-quarter 256.
// smem: Up2[128][6][32] float2 | HU_A[64][49] | HU_B[64][49] | sbias[48]
#define SM_UP2   49152
#define SM_HUA   (SM_UP2)
#define SM_HUB   (SM_HUA + 64 * HUSTR)
#define SM_BIAS  (SM_HUB + 64 * HUSTR)
#define GRU_SMEM ((SM_BIAS + 48 + 16) * 4)   // ~221.9 KB

__global__ __launch_bounds__(256, 1)
void gru_layer_kernel(int layer, const float* __restrict__ h0,
                      const float* __restrict__ U_raw,
                      const float* __restrict__ bias1,
                      float* __restrict__ yout, float* __restrict__ out_states,
                      int is_last) {
    extern __shared__ float sm[];
    float2* Up2   = (float2*)sm;
    float*  HUA   = sm + SM_HUA;
    float*  HUB   = sm + SM_HUB;
    float*  sbias = sm + SM_BIAS;

    const int tid  = threadIdx.x;
    const int lane = tid & 31, wid = tid >> 5;
    const int gid  = lane >> 2, tig = lane & 3;
    const int wm   = wid & 1, wk = wid >> 1;    // m-half, k-quarter
    const int mb   = wm * 32;
    const int kq   = wk * 32;                   // warp's first k8 index
    const int GQ   = wk * 16;                   // warp's first producer ugroup
    const int cm0  = mb + gid;
    const int cm1  = mb + 16 + gid;
    const int u0   = blockIdx.x * UB;
    const int bh   = blockIdx.y;
    const int b0g  = bh * MROWS;
    const unsigned ep = (unsigned)layer * LAYER_EP;

    // --- U slice, fragment-major (once per layer) ---
    const float* Uc = U_raw + (size_t)layer * UNITS * NC;
    for (int i = tid; i < 128 * 6 * 32; i += 256) {
        int l2   = i & 31;
        int nt   = (i >> 5) % 6;
        int k8   = i / (6 * 32);
        int ltig = l2 & 3, lgid = l2 >> 2;
        int col  = nt * 8 + lgid;
        int gate = col >> 4, uu = col & 15;
        size_t cofs = (size_t)gate * UNITS + u0 + uu;
        float v0 = tf32r(Uc[(size_t)(8 * k8 + ltig) * NC + cofs]);
        float v1 = tf32r(Uc[(size_t)(8 * k8 + ltig + 4) * NC + cofs]);
        Up2[i] = make_float2(v0, v1);
    }
    if (tid < CCOLS) {
        int gate = tid >> 4, uu = tid & 15;
        sbias[tid] = bias1[gate * UNITS + u0 + uu];
    }

    // epilogue cell ownership: b = b0g + (tid>>2), u = u0 + (tid&3)*4 + j
    const int eb  = b0g + (tid >> 2);
    const int eu4 = (tid & 3) * 4;

    // init h: full precision in regs, tf32 copy to g_hT[0]; publish via red.release
    float hreg[4];
    {
        const float* src = h0 + ((size_t)eb * UNITS + u0 + eu4) * LAYERS + layer;
        hreg[0] = src[0]; hreg[1] = src[3]; hreg[2] = src[6]; hreg[3] = src[9];
        g_hT[0][u0 + eu4 + 0][eb] = tf32r(hreg[0]);
        g_hT[0][u0 + eu4 + 1][eb] = tf32r(hreg[1]);
        g_hT[0][u0 + eu4 + 2][eb] = tf32r(hreg[2]);
        g_hT[0][u0 + eu4 + 3][eb] = tf32r(hreg[3]);
    }
    __syncthreads();
    red_release(&g_flag[bh][blockIdx.x]);   // each thread: state 0 published

#define PREFETCH(slot, step) do {                                              \
        const float* rp = hTp + (size_t)((kq + (step)) * 8 + tig) * BATCH;     \
        const float* rp4 = rp + 4 * BATCH;                                     \
        ar[slot][0][0] = __float_as_uint(rp[cm0]);                             \
        ar[slot][0][1] = __float_as_uint(rp[cm0 + 8]);                         \
        ar[slot][1][0] = __float_as_uint(rp[cm1]);                             \
        ar[slot][1][1] = __float_as_uint(rp[cm1 + 8]);                         \
        ar[slot][0][2] = __float_as_uint(rp4[cm0]);                            \
        ar[slot][0][3] = __float_as_uint(rp4[cm0 + 8]);                        \
        ar[slot][1][2] = __float_as_uint(rp4[cm1]);                            \
        ar[slot][1][3] = __float_as_uint(rp4[cm1 + 8]);                        \
    } while (0)

    for (int t = 0; t < TSEQ; t++) {
        const int rb = t & 1;
        const float* hTp = &g_hT[rb][0][b0g];
        const unsigned wt = ep + (unsigned)ARR * (t + 1);   // state t ready

        // prefetch epilogue operands (own data, no sync)
        const float* xwrow = g_xw + ((size_t)t * BATCH + eb) * NC + u0 + eu4;
        float4 xz4 = *(const float4*)(xwrow);
        float4 xr4 = *(const float4*)(xwrow + UNITS);
        float4 xh4 = *(const float4*)(xwrow + 2 * UNITS);

        float acc[2][6][4];
#pragma unroll
        for (int i = 0; i < 2; i++)
#pragma unroll
            for (int j = 0; j < 6; j++)
#pragma unroll
                for (int q = 0; q < 4; q++) acc[i][j][q] = 0.f;

        unsigned ar[8][2][4];
        wait_flag(&g_flag[bh][GQ], wt);
        PREFETCH(0, 0);
        PREFETCH(1, 1);
        wait_flag(&g_flag[bh][GQ + 1], wt);
        PREFETCH(2, 2);
        PREFETCH(3, 3);

#pragma unroll
        for (int u = 0; u < 32; u++) {
            // issue next prefetch FIRST (slot (u+4)&7, distance 4)
            if (u < 28) {
                if ((u & 1) == 0) wait_flag(&g_flag[bh][(kq + u + 4) >> 1], wt);
                PREFETCH((u + 4) & 7, u + 4);
            }
            const int gk8 = kq + u;
            unsigned bfr[6][2];
#pragma unroll
            for (int nt = 0; nt < 6; nt++) {
                float2 bq = Up2[(gk8 * 6 + nt) * 32 + lane];
                bfr[nt][0] = __float_as_uint(bq.x);
                bfr[nt][1] = __float_as_uint(bq.y);
            }
#pragma unroll
            for (int mt = 0; mt < 2; mt++)
#pragma unroll
                for (int nt = 0; nt < 6; nt++)
                    mma_tf32(acc[mt][nt], ar[u & 7][mt], bfr[nt]);
        }
        __syncthreads();   // prev epilogue done reading HU; safe to overwrite

        // 2 parallel merge passes: wk{0,2} write, wk{1,3} add
        float* HUd = (wk & 2) ? HUB : HUA;
        if ((wk & 1) == 0) {
#pragma unroll
            for (int mt = 0; mt < 2; mt++)
#pragma unroll
                for (int nt = 0; nt < 6; nt++) {
                    int m = mb + mt * 16 + gid;
                    int n = nt * 8 + 2 * tig;
                    HUd[m * HUSTR + n]           = acc[mt][nt][0];
                    HUd[m * HUSTR + n + 1]       = acc[mt][nt][1];
                    HUd[(m + 8) * HUSTR + n]     = acc[mt][nt][2];
                    HUd[(m + 8) * HUSTR + n + 1] = acc[mt][nt][3];
                }
        }
        __syncthreads();
        if ((wk & 1) == 1) {
#pragma unroll
            for (int mt = 0; mt < 2; mt++)
#pragma unroll
                for (int nt = 0; nt < 6; nt++) {
                    int m = mb + mt * 16 + gid;
                    int n = nt * 8 + 2 * tig;
                    HUd[m * HUSTR + n]           += acc[mt][nt][0];
                    HUd[m * HUSTR + n + 1]       += acc[mt][nt][1];
                    HUd[(m + 8) * HUSTR + n]     += acc[mt][nt][2];
                    HUd[(m + 8) * HUSTR + n + 1] += acc[mt][nt][3];
                }
        }
        __syncthreads();

        // gate epilogue: 4 cells per thread; publish via per-thread red.release
        const int wb = 1 - rb;
        const int m  = tid >> 2;
        float hn4[4];
        const float xz[4] = {xz4.x, xz4.y, xz4.z, xz4.w};
        const float xr[4] = {xr4.x, xr4.y, xr4.z, xr4.w};
        const float xh[4] = {xh4.x, xh4.y, xh4.z, xh4.w};
#pragma unroll
        for (int j = 0; j < 4; j++) {
            int uu = eu4 + j;
            float hz = HUA[m * HUSTR + uu]          + HUB[m * HUSTR + uu]          + sbias[uu];
            float hr = HUA[m * HUSTR + UB + uu]     + HUB[m * HUSTR + UB + uu]     + sbias[UB + uu];
            float hh = HUA[m * HUSTR + 2 * UB + uu] + HUB[m * HUSTR + 2 * UB + uu] + sbias[2 * UB + uu];
            float z    = 1.f / (1.f + __expf(-(xz[j] + hz)));
            float rg   = 1.f / (1.f + __expf(-(xr[j] + hr)));
            float hhat = tanhf(xh[j] + rg * hh);
            float hn   = z * hreg[j] + (1.f - z) * hhat;
            hreg[j] = hn;
            hn4[j] = hn;
            g_hT[wb][u0 + uu][eb] = tf32r(hn);
        }
        size_t yi = ((size_t)eb * TSEQ + t) * UNITS + u0 + eu4;
        if (is_last) {
            *(float4*)(yout + yi) = make_float4(hn4[0], hn4[1], hn4[2], hn4[3]);
        } else {
            *(float4*)(g_x + yi) =
                make_float4(tf32r(hn4[0]), tf32r(hn4[1]), tf32r(hn4[2]), tf32r(hn4[3]));
        }
        red_release(&g_flag[bh][blockIdx.x]);   // this thread's state t+1 stores ordered
    }
#undef PREFETCH

    // final states (from full-precision registers)
    {
        float* d = out_states + ((size_t)eb * UNITS + u0 + eu4) * LAYERS + layer;
        d[0] = hreg[0]; d[3] = hreg[1]; d[6] = hreg[2]; d[9] = hreg[3];
    }
}

// ---------------- host launcher ----------------
extern "C" void kernel_launch(void* const* d_in, const int* in_sizes, int n_in,
                              void* d_out, int out_size) {
    (void)in_sizes; (void)n_in; (void)out_size;
    const float* x_in = (const float*)d_in[0];
    const float* h0   = (const float*)d_in[1];
    const float* W    = (const float*)d_in[2];
    const float* U    = (const float*)d_in[3];
    const float* b    = (const float*)d_in[4];
    float* out        = (float*)d_out;
    float* out_states = out + (size_t)MXW * UNITS;

    static float* g_x_ptr = nullptr;
    static float* g_Wc_ptr = nullptr;
    if (!g_x_ptr)  cudaGetSymbolAddress((void**)&g_x_ptr, g_x);
    if (!g_Wc_ptr) cudaGetSymbolAddress((void**)&g_Wc_ptr, g_Wc);

    cudaFuncSetAttribute(gru_layer_kernel,
                         cudaFuncAttributeMaxDynamicSharedMemorySize, GRU_SMEM);
    cudaFuncSetAttribute(gemm_xw_kernel,
                         cudaFuncAttributeMaxDynamicSharedMemorySize, XW_SMEM);

    cvt_weights_kernel<<<4096, 256>>>(W);   // also resets flags each replay
    cvt_input_kernel<<<8192, 256>>>(x_in);

    for (int l = 0; l < LAYERS; l++) {
        gemm_xw_kernel<<<dim3(NC / BN, MXW / BM), 256, XW_SMEM>>>(
            g_x_ptr, g_Wc_ptr + (size_t)l * UNITS * NC, b + (size_t)l * 2 * NC);
        gru_layer_kernel<<<dim3(UGRP, 2), 256, GRU_SMEM>>>(
            l, h0, U, b + (size_t)l * 2 * NC + NC, out, out_states, l == LAYERS - 1);
    }
}

// round 12
// speedup vs baseline: 2.0448x; 1.4050x over previous
#include <cuda_runtime.h>
#include <cstdint>
#include <math.h>

#define LAYERS 3
#define UNITS  1024
#define BATCH  128
#define TSEQ   256
#define NC     (3*UNITS)      // 3072
#define MXW    (BATCH*TSEQ)   // 32768

// recurrent geometry: grid = 64 u-groups x 2 batch-halves = 128 CTAs (co-resident)
#define UGRP   64
#define UB     16
#define CCOLS  48
#define MROWS  64
#define HUSTR  49
#define ARR    256                      // flag arrivals per CTA per state
#define LAYER_EP (ARR * (TSEQ + 1))     // flag epoch stride per layer

// ---------------- scratch (static device memory) ----------------
__device__ __align__(128) float g_xw[(size_t)MXW * NC];      // [t][b][3U]
__device__ __align__(128) float g_x [(size_t)MXW * UNITS];   // activations (tf32-rounded)
__device__ __align__(128) float g_Wc[(size_t)LAYERS * UNITS * NC]; // tf32-rounded W
__device__ __align__(128) float g_hT[2][UNITS][BATCH];       // tf32 h, transposed
__device__ unsigned g_flag[2][UGRP];                         // [half][ugroup]

// ---------------- helpers ----------------
__device__ __forceinline__ float tf32r(float v) {
    unsigned r;
    asm("cvt.rna.tf32.f32 %0, %1;" : "=r"(r) : "f"(v));
    return __uint_as_float(r);
}

__device__ __forceinline__ void mma_tf32(float* c, const unsigned* a, const unsigned* b) {
    asm volatile(
        "mma.sync.aligned.m16n8k8.row.col.f32.tf32.tf32.f32 "
        "{%0,%1,%2,%3}, {%4,%5,%6,%7}, {%8,%9}, {%0,%1,%2,%3};"
        : "+f"(c[0]), "+f"(c[1]), "+f"(c[2]), "+f"(c[3])
        : "r"(a[0]), "r"(a[1]), "r"(a[2]), "r"(a[3]), "r"(b[0]), "r"(b[1]));
}

__device__ __forceinline__ unsigned ldacq(const unsigned* p) {
    unsigned v;
    asm volatile("ld.acquire.gpu.global.u32 %0, [%1];" : "=r"(v) : "l"(p));
    return v;
}
__device__ __forceinline__ void red_release(unsigned* p) {
    asm volatile("red.release.gpu.global.add.u32 [%0], 1;" :: "l"(p));
}
__device__ __forceinline__ void wait_flag(const unsigned* p, unsigned thr) {
    while (ldacq(p) < thr) {}
}

// ---------------- conversion kernels (also reset flags each replay) ----------------
__global__ void cvt_weights_kernel(const float* __restrict__ W) {
    if (blockIdx.x == 0 && threadIdx.x < 2 * UGRP)
        ((unsigned*)g_flag)[threadIdx.x] = 0u;
    size_t n = (size_t)LAYERS * UNITS * NC;
    for (size_t i = blockIdx.x * (size_t)blockDim.x + threadIdx.x; i < n;
         i += (size_t)gridDim.x * blockDim.x)
        g_Wc[i] = tf32r(W[i]);
}
__global__ void cvt_input_kernel(const float* __restrict__ X) {
    size_t n = (size_t)MXW * UNITS;
    for (size_t i = blockIdx.x * (size_t)blockDim.x + threadIdx.x; i < n;
         i += (size_t)gridDim.x * blockDim.x)
        g_x[i] = tf32r(X[i]);
}

// ---------------- XW GEMM: register-double-buffered LDG->STS pipeline ----------------
// A smem [m][36], B smem [k][136], 2 smem stages, 2 CTAs/SM.
// A: thread t covers row (t>>1), k = 16*(t&1) + {0..15}  (4 float4)  -> full 128x32 tile
// B: thread t covers row (t>>3), cols 4*(t&7) + {0,32,64,96} (4 float4) -> full 32x128 tile
#define BM 128
#define BN 128
#define BK 32
#define XA_STR 36
#define XB_STR 136
#define XA_SZ (BM * XA_STR)          // 4608 floats
#define XB_SZ (BK * XB_STR)          // 4352 floats
#define X_STAGE (XA_SZ + XB_SZ)      // 8960 floats
#define XW_SMEM (2 * X_STAGE * 4)    // 71680 bytes -> 2 CTAs/SM

__global__ __launch_bounds__(256, 2) void gemm_xw_kernel(const float* __restrict__ A,
                                                         const float* __restrict__ Bw,
                                                         const float* __restrict__ bias) {
    extern __shared__ float smx[];
    float* C = g_xw;

    const int tid = threadIdx.x;
    const int lane = tid & 31, wid = tid >> 5;
    const int gid = lane >> 2, tig = lane & 3;
    const int wm = wid & 3, wn = wid >> 2;
    const int mb = wm * 32, nb = wn * 64;
    const int bm0 = blockIdx.y * BM, bn0 = blockIdx.x * BN;

    float acc[2][8][4];
#pragma unroll
    for (int i = 0; i < 2; i++)
#pragma unroll
        for (int j = 0; j < 8; j++)
#pragma unroll
            for (int q = 0; q < 4; q++) acc[i][j][q] = 0.f;

    float4 la0, la1, la2, la3, lb0, lb1, lb2, lb3;
#define XW_LDG(k0) do {                                                          \
        const float* arow = A + (size_t)(bm0 + (tid >> 1)) * UNITS + (k0) + (tid & 1) * 16; \
        la0 = *(const float4*)(arow);                                            \
        la1 = *(const float4*)(arow + 4);                                        \
        la2 = *(const float4*)(arow + 8);                                        \
        la3 = *(const float4*)(arow + 12);                                       \
        const float* brow = Bw + (size_t)((k0) + (tid >> 3)) * NC + bn0 + (tid & 7) * 4; \
        lb0 = *(const float4*)(brow);                                            \
        lb1 = *(const float4*)(brow + 32);                                       \
        lb2 = *(const float4*)(brow + 64);                                       \
        lb3 = *(const float4*)(brow + 96);                                       \
    } while (0)
#define XW_STS(buf) do {                                                         \
        float* As2 = smx + (buf) * X_STAGE;                                      \
        float* Bs2 = As2 + XA_SZ;                                                \
        float* ad = As2 + (tid >> 1) * XA_STR + (tid & 1) * 16;                  \
        *(float4*)(ad)      = la0;                                               \
        *(float4*)(ad + 4)  = la1;                                               \
        *(float4*)(ad + 8)  = la2;                                               \
        *(float4*)(ad + 12) = la3;                                               \
        float* bd = Bs2 + (tid >> 3) * XB_STR + (tid & 7) * 4;                   \
        *(float4*)(bd)      = lb0;                                               \
        *(float4*)(bd + 32) = lb1;                                               \
        *(float4*)(bd + 64) = lb2;                                               \
        *(float4*)(bd + 96) = lb3;                                               \
    } while (0)

    XW_LDG(0);
    XW_STS(0);
    XW_LDG(BK);
    __syncthreads();

    const int NIT = UNITS / BK;   // 32
    for (int it = 0; it < NIT; it++) {
        const float* As2 = smx + (it & 1) * X_STAGE;
        const float* Bs2 = As2 + XA_SZ;
#pragma unroll
        for (int kk = 0; kk < BK; kk += 8) {
            unsigned a[2][4], bf[8][2];
#pragma unroll
            for (int mt = 0; mt < 2; mt++) {
                int m = mb + mt * 16 + gid;
                a[mt][0] = __float_as_uint(As2[m * XA_STR + kk + tig]);
                a[mt][1] = __float_as_uint(As2[(m + 8) * XA_STR + kk + tig]);
                a[mt][2] = __float_as_uint(As2[m * XA_STR + kk + tig + 4]);
                a[mt][3] = __float_as_uint(As2[(m + 8) * XA_STR + kk + tig + 4]);
            }
#pragma unroll
            for (int nt = 0; nt < 8; nt++) {
                int n = nb + nt * 8 + gid;
                bf[nt][0] = __float_as_uint(Bs2[(kk + tig) * XB_STR + n]);
                bf[nt][1] = __float_as_uint(Bs2[(kk + tig + 4) * XB_STR + n]);
            }
#pragma unroll
            for (int mt = 0; mt < 2; mt++)
#pragma unroll
                for (int nt = 0; nt < 8; nt++) mma_tf32(acc[mt][nt], a[mt], bf[nt]);
        }
        __syncthreads();                 // everyone done reading stage it&1
        if (it + 1 < NIT) {
            XW_STS((it + 1) & 1);        // regs hold tile it+1
            if (it + 2 < NIT) XW_LDG((it + 2) * BK);
            __syncthreads();             // STS visible before next compute
        }
    }
#undef XW_LDG
#undef XW_STS

#pragma unroll
    for (int mt = 0; mt < 2; mt++) {
#pragma unroll
        for (int nt = 0; nt < 8; nt++) {
            int m0 = bm0 + mb + mt * 16 + gid;    // row = b*TSEQ + t
            int n  = bn0 + nb + nt * 8 + 2 * tig;
            float bv0 = bias[n], bv1 = bias[n + 1];
            int t0 = m0 & (TSEQ - 1), b0r = m0 >> 8;
            int m1 = m0 + 8;
            int t1 = m1 & (TSEQ - 1), b1r = m1 >> 8;
            size_t r0 = ((size_t)t0 * BATCH + b0r) * NC + n;
            size_t r1 = ((size_t)t1 * BATCH + b1r) * NC + n;
            C[r0]     = acc[mt][nt][0] + bv0;
            C[r0 + 1] = acc[mt][nt][1] + bv1;
            C[r1]     = acc[mt][nt][2] + bv0;
            C[r1 + 1] = acc[mt][nt][3] + bv1;
        }
    }
}

// ---------------- persistent GRU layer kernel ----------------
// 8 warps: wm(2) x wk(4). Batch-permuted A cols: logical m = 32*wm + gid + 8*s
// lives at physical col 32*wm + 4*gid + s  ->  one LDG.128 = 4 A-regs.
#define SM_UP2   49152
#define SM_HUA   (SM_UP2)
#define SM_HUB   (SM_HUA + 64 * HUSTR)
#define SM_BIAS  (SM_HUB + 64 * HUSTR)
#define GRU_SMEM ((SM_BIAS + 48 + 16) * 4)

__global__ __launch_bounds__(256, 1)
void gru_layer_kernel(int layer, const float* __restrict__ h0,
                      const float* __restrict__ U_raw,
                      const float* __restrict__ bias1,
                      float* __restrict__ yout, float* __restrict__ out_states,
                      int is_last) {
    extern __shared__ float sm[];
    float2* Up2   = (float2*)sm;
    float*  HUA   = sm + SM_HUA;
    float*  HUB   = sm + SM_HUB;
    float*  sbias = sm + SM_BIAS;

    const int tid  = threadIdx.x;
    const int lane = tid & 31, wid = tid >> 5;
    const int gid  = lane >> 2, tig = lane & 3;
    const int wm   = wid & 1, wk = wid >> 1;    // m-half, k-quarter
    const int mb   = wm * 32;
    const int kq   = wk * 32;                   // warp's first k8 index
    const int GQ   = wk * 16;                   // warp's first producer ugroup
    const int cph  = wm * 32 + 4 * gid;         // physical col base for LDG.128
    const int u0   = blockIdx.x * UB;
    const int bh   = blockIdx.y;
    const int b0g  = bh * MROWS;
    const unsigned ep = (unsigned)layer * LAYER_EP;

    // --- U slice, fragment-major (once per layer) ---
    const float* Uc = U_raw + (size_t)layer * UNITS * NC;
    for (int i = tid; i < 128 * 6 * 32; i += 256) {
        int l2   = i & 31;
        int nt   = (i >> 5) % 6;
        int k8   = i / (6 * 32);
        int ltig = l2 & 3, lgid = l2 >> 2;
        int col  = nt * 8 + lgid;
        int gate = col >> 4, uu = col & 15;
        size_t cofs = (size_t)gate * UNITS + u0 + uu;
        float v0 = tf32r(Uc[(size_t)(8 * k8 + ltig) * NC + cofs]);
        float v1 = tf32r(Uc[(size_t)(8 * k8 + ltig + 4) * NC + cofs]);
        Up2[i] = make_float2(v0, v1);
    }
    if (tid < CCOLS) {
        int gate = tid >> 4, uu = tid & 15;
        sbias[tid] = bias1[gate * UNITS + u0 + uu];
    }

    // epilogue: thread owns actual batch eb, u = u0 + (tid&3)*4 + j.
    // HU rows are LOGICAL m; inverse permutation of pb = tid>>2:
    //   pb = 32*w + 4*g + s  ->  m_log = 32*w + g + 8*s
    const int pb   = tid >> 2;
    const int eb   = b0g + pb;
    const int eu4  = (tid & 3) * 4;
    const int mlog = ((pb >> 5) << 5) + ((pb >> 2) & 7) + ((pb & 3) << 3);

    // init h: full precision in regs, tf32 copy to g_hT[0]
    float hreg[4];
    {
        const float* src = h0 + ((size_t)eb * UNITS + u0 + eu4) * LAYERS + layer;
        hreg[0] = src[0]; hreg[1] = src[3]; hreg[2] = src[6]; hreg[3] = src[9];
        g_hT[0][u0 + eu4 + 0][eb] = tf32r(hreg[0]);
        g_hT[0][u0 + eu4 + 1][eb] = tf32r(hreg[1]);
        g_hT[0][u0 + eu4 + 2][eb] = tf32r(hreg[2]);
        g_hT[0][u0 + eu4 + 3][eb] = tf32r(hreg[3]);
    }
    __syncthreads();
    red_release(&g_flag[bh][blockIdx.x]);

// one slot = 2 LDG.128: rows (k8*8+tig) and (+4), cols cph..cph+3 (physical)
// v.x->a[0][0](m=mb+gid) v.y->a[0][1](mb+8+gid) v.z->a[1][0](mb+16+gid) v.w->a[1][1](mb+24+gid)
#define PREFETCH(slot, step) do {                                              \
        const float* rp = hTp + (size_t)((kq + (step)) * 8 + tig) * BATCH + cph; \
        float4 v0 = *(const float4*)(rp);                                      \
        float4 v1 = *(const float4*)(rp + 4 * BATCH);                          \
        ar[slot][0][0] = __float_as_uint(v0.x);                                \
        ar[slot][0][1] = __float_as_uint(v0.y);                                \
        ar[slot][1][0] = __float_as_uint(v0.z);                                \
        ar[slot][1][1] = __float_as_uint(v0.w);                                \
        ar[slot][0][2] = __float_as_uint(v1.x);                                \
        ar[slot][0][3] = __float_as_uint(v1.y);                                \
        ar[slot][1][2] = __float_as_uint(v1.z);                                \
        ar[slot][1][3] = __float_as_uint(v1.w);                                \
    } while (0)

    for (int t = 0; t < TSEQ; t++) {
        const int rb = t & 1;
        const float* hTp = &g_hT[rb][0][b0g];
        const unsigned wt = ep + (unsigned)ARR * (t + 1);

        const float* xwrow = g_xw + ((size_t)t * BATCH + eb) * NC + u0 + eu4;
        float4 xz4 = *(const float4*)(xwrow);
        float4 xr4 = *(const float4*)(xwrow + UNITS);
        float4 xh4 = *(const float4*)(xwrow + 2 * UNITS);

        float acc[2][6][4];
#pragma unroll
        for (int i = 0; i < 2; i++)
#pragma unroll
            for (int j = 0; j < 6; j++)
#pragma unroll
                for (int q = 0; q < 4; q++) acc[i][j][q] = 0.f;

        unsigned ar[8][2][4];
        wait_flag(&g_flag[bh][GQ], wt);
        PREFETCH(0, 0);
        PREFETCH(1, 1);
        wait_flag(&g_flag[bh][GQ + 1], wt);
        PREFETCH(2, 2);
        PREFETCH(3, 3);

#pragma unroll
        for (int u = 0; u < 32; u++) {
            if (u < 28) {
                if ((u & 1) == 0) wait_flag(&g_flag[bh][(kq + u + 4) >> 1], wt);
                PREFETCH((u + 4) & 7, u + 4);
            }
            const int gk8 = kq + u;
            unsigned bfr[6][2];
#pragma unroll
            for (int nt = 0; nt < 6; nt++) {
                float2 bq = Up2[(gk8 * 6 + nt) * 32 + lane];
                bfr[nt][0] = __float_as_uint(bq.x);
                bfr[nt][1] = __float_as_uint(bq.y);
            }
#pragma unroll
            for (int mt = 0; mt < 2; mt++)
#pragma unroll
                for (int nt = 0; nt < 6; nt++)
                    mma_tf32(acc[mt][nt], ar[u & 7][mt], bfr[nt]);
        }
        __syncthreads();

        // 2 parallel merge passes (logical m rows)
        float* HUd = (wk & 2) ? HUB : HUA;
        if ((wk & 1) == 0) {
#pragma unroll
            for (int mt = 0; mt < 2; mt++)
#pragma unroll
                for (int nt = 0; nt < 6; nt++) {
                    int m = mb + mt * 16 + gid;
                    int n = nt * 8 + 2 * tig;
                    HUd[m * HUSTR + n]           = acc[mt][nt][0];
                    HUd[m * HUSTR + n + 1]       = acc[mt][nt][1];
                    HUd[(m + 8) * HUSTR + n]     = acc[mt][nt][2];
                    HUd[(m + 8) * HUSTR + n + 1] = acc[mt][nt][3];
                }
        }
        __syncthreads();
        if ((wk & 1) == 1) {
#pragma unroll
            for (int mt = 0; mt < 2; mt++)
#pragma unroll
                for (int nt = 0; nt < 6; nt++) {
                    int m = mb + mt * 16 + gid;
                    int n = nt * 8 + 2 * tig;
                    HUd[m * HUSTR + n]           += acc[mt][nt][0];
                    HUd[m * HUSTR + n + 1]       += acc[mt][nt][1];
                    HUd[(m + 8) * HUSTR + n]     += acc[mt][nt][2];
                    HUd[(m + 8) * HUSTR + n + 1] += acc[mt][nt][3];
                }
        }
        __syncthreads();

        // gate epilogue (HU indexed by logical m via inverse permutation)
        const int wb = 1 - rb;
        float hn4[4];
        const float xz[4] = {xz4.x, xz4.y, xz4.z, xz4.w};
        const float xr[4] = {xr4.x, xr4.y, xr4.z, xr4.w};
        const float xh[4] = {xh4.x, xh4.y, xh4.z, xh4.w};
#pragma unroll
        for (int j = 0; j < 4; j++) {
            int uu = eu4 + j;
            float hz = HUA[mlog * HUSTR + uu]          + HUB[mlog * HUSTR + uu]          + sbias[uu];
            float hr = HUA[mlog * HUSTR + UB + uu]     + HUB[mlog * HUSTR + UB + uu]     + sbias[UB + uu];
            float hh = HUA[mlog * HUSTR + 2 * UB + uu] + HUB[mlog * HUSTR + 2 * UB + uu] + sbias[2 * UB + uu];
            float z    = 1.f / (1.f + __expf(-(xz[j] + hz)));
            float rg   = 1.f / (1.f + __expf(-(xr[j] + hr)));
            float hhat = tanhf(xh[j] + rg * hh);
            float hn   = z * hreg[j] + (1.f - z) * hhat;
            hreg[j] = hn;
            hn4[j] = hn;
            g_hT[wb][u0 + uu][eb] = tf32r(hn);
        }
        size_t yi = ((size_t)eb * TSEQ + t) * UNITS + u0 + eu4;
        if (is_last) {
            *(float4*)(yout + yi) = make_float4(hn4[0], hn4[1], hn4[2], hn4[3]);
        } else {
            *(float4*)(g_x + yi) =
                make_float4(tf32r(hn4[0]), tf32r(hn4[1]), tf32r(hn4[2]), tf32r(hn4[3]));
        }
        red_release(&g_flag[bh][blockIdx.x]);
    }
#undef PREFETCH

    // final states
    {
        float* d = out_states + ((size_t)eb * UNITS + u0 + eu4) * LAYERS + layer;
        d[0] = hreg[0]; d[3] = hreg[1]; d[6] = hreg[2]; d[9] = hreg[3];
    }
}

// ---------------- host launcher ----------------
extern "C" void kernel_launch(void* const* d_in, const int* in_sizes, int n_in,
                              void* d_out, int out_size) {
    (void)in_sizes; (void)n_in; (void)out_size;
    const float* x_in = (const float*)d_in[0];
    const float* h0   = (const float*)d_in[1];
    const float* W    = (const float*)d_in[2];
    const float* U    = (const float*)d_in[3];
    const float* b    = (const float*)d_in[4];
    float* out        = (float*)d_out;
    float* out_states = out + (size_t)MXW * UNITS;

    static float* g_x_ptr = nullptr;
    static float* g_Wc_ptr = nullptr;
    if (!g_x_ptr)  cudaGetSymbolAddress((void**)&g_x_ptr, g_x);
    if (!g_Wc_ptr) cudaGetSymbolAddress((void**)&g_Wc_ptr, g_Wc);

    cudaFuncSetAttribute(gru_layer_kernel,
                         cudaFuncAttributeMaxDynamicSharedMemorySize, GRU_SMEM);
    cudaFuncSetAttribute(gemm_xw_kernel,
                         cudaFuncAttributeMaxDynamicSharedMemorySize, XW_SMEM);

    cvt_weights_kernel<<<4096, 256>>>(W);   // also resets flags each replay
    cvt_input_kernel<<<8192, 256>>>(x_in);

    for (int l = 0; l < LAYERS; l++) {
        gemm_xw_kernel<<<dim3(NC / BN, MXW / BM), 256, XW_SMEM>>>(
            g_x_ptr, g_Wc_ptr + (size_t)l * UNITS * NC, b + (size_t)l * 2 * NC);
        gru_layer_kernel<<<dim3(UGRP, 2), 256, GRU_SMEM>>>(
            l, h0, U, b + (size_t)l * 2 * NC + NC, out, out_states, l == LAYERS - 1);
    }
}

// round 13
// speedup vs baseline: 2.1798x; 1.0660x over previous
#include <cuda_runtime.h>
#include <cstdint>
#include <math.h>

#define LAYERS 3
#define UNITS  1024
#define BATCH  128
#define TSEQ   256
#define NC     (3*UNITS)      // 3072
#define MXW    (BATCH*TSEQ)   // 32768

// recurrent geometry: grid = 64 u-groups x 2 batch-halves = 128 CTAs (co-resident)
#define UGRP   64
#define UB     16
#define CCOLS  48
#define MROWS  64
#define HUSTR  49
#define ARR    256                      // flag arrivals per CTA per state
#define LAYER_EP (ARR * (TSEQ + 1))     // flag epoch stride per layer
#define GRU_THREADS 288                 // 8 compute warps + 1 watcher warp

// ---------------- scratch (static device memory) ----------------
__device__ __align__(128) float g_xw[(size_t)MXW * NC];      // [t][b][3U]
__device__ __align__(128) float g_x [(size_t)MXW * UNITS];   // activations (tf32-rounded)
__device__ __align__(128) float g_Wc[(size_t)LAYERS * UNITS * NC]; // tf32-rounded W
__device__ __align__(128) float g_hT[2][UNITS][BATCH];       // tf32 h, transposed
__device__ unsigned g_flag[2][UGRP];                         // [half][ugroup]

// ---------------- helpers ----------------
__device__ __forceinline__ float tf32r(float v) {
    unsigned r;
    asm("cvt.rna.tf32.f32 %0, %1;" : "=r"(r) : "f"(v));
    return __uint_as_float(r);
}

__device__ __forceinline__ void mma_tf32(float* c, const unsigned* a, const unsigned* b) {
    asm volatile(
        "mma.sync.aligned.m16n8k8.row.col.f32.tf32.tf32.f32 "
        "{%0,%1,%2,%3}, {%4,%5,%6,%7}, {%8,%9}, {%0,%1,%2,%3};"
        : "+f"(c[0]), "+f"(c[1]), "+f"(c[2]), "+f"(c[3])
        : "r"(a[0]), "r"(a[1]), "r"(a[2]), "r"(a[3]), "r"(b[0]), "r"(b[1]));
}

__device__ __forceinline__ unsigned ldacq_gpu(const unsigned* p) {
    unsigned v;
    asm volatile("ld.acquire.gpu.global.u32 %0, [%1];" : "=r"(v) : "l"(p));
    return v;
}
__device__ __forceinline__ void red_release(unsigned* p) {
    asm volatile("red.release.gpu.global.add.u32 [%0], 1;" :: "l"(p));
}
__device__ __forceinline__ uint32_t smem_u32(const void* p) {
    return (uint32_t)__cvta_generic_to_shared(p);
}
__device__ __forceinline__ unsigned lds_acq(uint32_t a) {
    unsigned v;
    asm volatile("ld.acquire.cta.shared.u32 %0, [%1];" : "=r"(v) : "r"(a));
    return v;
}
__device__ __forceinline__ void sts_rel(uint32_t a, unsigned v) {
    asm volatile("st.release.cta.shared.u32 [%0], %1;" :: "r"(a), "r"(v) : "memory");
}
// compute-warp wait on smem flag mirror (cheap LDS polls)
__device__ __forceinline__ void wait_sflag(uint32_t addr, unsigned thr) {
    while (lds_acq(addr) < thr) {}
}
#define NB_SYNC() asm volatile("bar.sync 1, 256;" ::: "memory")

// ---------------- conversion kernels (also reset flags each replay) ----------------
__global__ void cvt_weights_kernel(const float* __restrict__ W) {
    if (blockIdx.x == 0 && threadIdx.x < 2 * UGRP)
        ((unsigned*)g_flag)[threadIdx.x] = 0u;
    size_t n = (size_t)LAYERS * UNITS * NC;
    for (size_t i = blockIdx.x * (size_t)blockDim.x + threadIdx.x; i < n;
         i += (size_t)gridDim.x * blockDim.x)
        g_Wc[i] = tf32r(W[i]);
}
__global__ void cvt_input_kernel(const float* __restrict__ X) {
    size_t n = (size_t)MXW * UNITS;
    for (size_t i = blockIdx.x * (size_t)blockDim.x + threadIdx.x; i < n;
         i += (size_t)gridDim.x * blockDim.x)
        g_x[i] = tf32r(X[i]);
}

// ---------------- XW GEMM: register-double-buffered LDG->STS pipeline ----------------
#define BM 128
#define BN 128
#define BK 32
#define XA_STR 36
#define XB_STR 136
#define XA_SZ (BM * XA_STR)
#define XB_SZ (BK * XB_STR)
#define X_STAGE (XA_SZ + XB_SZ)
#define XW_SMEM (2 * X_STAGE * 4)    // 71680 bytes -> 2 CTAs/SM

__global__ __launch_bounds__(256, 2) void gemm_xw_kernel(const float* __restrict__ A,
                                                         const float* __restrict__ Bw,
                                                         const float* __restrict__ bias) {
    extern __shared__ float smx[];
    float* C = g_xw;

    const int tid = threadIdx.x;
    const int lane = tid & 31, wid = tid >> 5;
    const int gid = lane >> 2, tig = lane & 3;
    const int wm = wid & 3, wn = wid >> 2;
    const int mb = wm * 32, nb = wn * 64;
    const int bm0 = blockIdx.y * BM, bn0 = blockIdx.x * BN;

    float acc[2][8][4];
#pragma unroll
    for (int i = 0; i < 2; i++)
#pragma unroll
        for (int j = 0; j < 8; j++)
#pragma unroll
            for (int q = 0; q < 4; q++) acc[i][j][q] = 0.f;

    float4 la0, la1, la2, la3, lb0, lb1, lb2, lb3;
#define XW_LDG(k0) do {                                                          \
        const float* arow = A + (size_t)(bm0 + (tid >> 1)) * UNITS + (k0) + (tid & 1) * 16; \
        la0 = *(const float4*)(arow);                                            \
        la1 = *(const float4*)(arow + 4);                                        \
        la2 = *(const float4*)(arow + 8);                                        \
        la3 = *(const float4*)(arow + 12);                                       \
        const float* brow = Bw + (size_t)((k0) + (tid >> 3)) * NC + bn0 + (tid & 7) * 4; \
        lb0 = *(const float4*)(brow);                                            \
        lb1 = *(const float4*)(brow + 32);                                       \
        lb2 = *(const float4*)(brow + 64);                                       \
        lb3 = *(const float4*)(brow + 96);                                       \
    } while (0)
#define XW_STS(buf) do {                                                         \
        float* As2 = smx + (buf) * X_STAGE;                                      \
        float* Bs2 = As2 + XA_SZ;                                                \
        float* ad = As2 + (tid >> 1) * XA_STR + (tid & 1) * 16;                  \
        *(float4*)(ad)      = la0;                                               \
        *(float4*)(ad + 4)  = la1;                                               \
        *(float4*)(ad + 8)  = la2;                                               \
        *(float4*)(ad + 12) = la3;                                               \
        float* bd = Bs2 + (tid >> 3) * XB_STR + (tid & 7) * 4;                   \
        *(float4*)(bd)      = lb0;                                               \
        *(float4*)(bd + 32) = lb1;                                               \
        *(float4*)(bd + 64) = lb2;                                               \
        *(float4*)(bd + 96) = lb3;                                               \
    } while (0)

    XW_LDG(0);
    XW_STS(0);
    XW_LDG(BK);
    __syncthreads();

    const int NIT = UNITS / BK;   // 32
    for (int it = 0; it < NIT; it++) {
        const float* As2 = smx + (it & 1) * X_STAGE;
        const float* Bs2 = As2 + XA_SZ;
#pragma unroll
        for (int kk = 0; kk < BK; kk += 8) {
            unsigned a[2][4], bf[8][2];
#pragma unroll
            for (int mt = 0; mt < 2; mt++) {
                int m = mb + mt * 16 + gid;
                a[mt][0] = __float_as_uint(As2[m * XA_STR + kk + tig]);
                a[mt][1] = __float_as_uint(As2[(m + 8) * XA_STR + kk + tig]);
                a[mt][2] = __float_as_uint(As2[m * XA_STR + kk + tig + 4]);
                a[mt][3] = __float_as_uint(As2[(m + 8) * XA_STR + kk + tig + 4]);
            }
#pragma unroll
            for (int nt = 0; nt < 8; nt++) {
                int n = nb + nt * 8 + gid;
                bf[nt][0] = __float_as_uint(Bs2[(kk + tig) * XB_STR + n]);
                bf[nt][1] = __float_as_uint(Bs2[(kk + tig + 4) * XB_STR + n]);
            }
#pragma unroll
            for (int mt = 0; mt < 2; mt++)
#pragma unroll
                for (int nt = 0; nt < 8; nt++) mma_tf32(acc[mt][nt], a[mt], bf[nt]);
        }
        __syncthreads();
        if (it + 1 < NIT) {
            XW_STS((it + 1) & 1);
            if (it + 2 < NIT) XW_LDG((it + 2) * BK);
            __syncthreads();
        }
    }
#undef XW_LDG
#undef XW_STS

#pragma unroll
    for (int mt = 0; mt < 2; mt++) {
#pragma unroll
        for (int nt = 0; nt < 8; nt++) {
            int m0 = bm0 + mb + mt * 16 + gid;    // row = b*TSEQ + t
            int n  = bn0 + nb + nt * 8 + 2 * tig;
            float bv0 = bias[n], bv1 = bias[n + 1];
            int t0 = m0 & (TSEQ - 1), b0r = m0 >> 8;
            int m1 = m0 + 8;
            int t1 = m1 & (TSEQ - 1), b1r = m1 >> 8;
            size_t r0 = ((size_t)t0 * BATCH + b0r) * NC + n;
            size_t r1 = ((size_t)t1 * BATCH + b1r) * NC + n;
            C[r0]     = acc[mt][nt][0] + bv0;
            C[r0 + 1] = acc[mt][nt][1] + bv1;
            C[r1]     = acc[mt][nt][2] + bv0;
            C[r1 + 1] = acc[mt][nt][3] + bv1;
        }
    }
}

// ---------------- persistent GRU layer kernel (watcher-warp flag mirroring) ----------------
// 8 compute warps: wm(2) x wk(4), batch-permuted LDG.128 A-frags; warp 8 = flag watcher.
#define SM_UP2   49152
#define SM_HUA   (SM_UP2)
#define SM_HUB   (SM_HUA + 64 * HUSTR)
#define SM_BIAS  (SM_HUB + 64 * HUSTR)
#define SM_FLAG  (SM_BIAS + 48)                 // 64 unsigned mirror
#define GRU_SMEM ((SM_FLAG + 64 + 16) * 4)

__global__ __launch_bounds__(GRU_THREADS, 1)
void gru_layer_kernel(int layer, const float* __restrict__ h0,
                      const float* __restrict__ U_raw,
                      const float* __restrict__ bias1,
                      float* __restrict__ yout, float* __restrict__ out_states,
                      int is_last) {
    extern __shared__ float sm[];
    float2* Up2    = (float2*)sm;
    float*  HUA    = sm + SM_HUA;
    float*  HUB    = sm + SM_HUB;
    float*  sbias  = sm + SM_BIAS;
    unsigned* sflag = (unsigned*)(sm + SM_FLAG);

    const int tid  = threadIdx.x;
    const int lane = tid & 31, wid = tid >> 5;
    const int gid  = lane >> 2, tig = lane & 3;
    const int u0   = blockIdx.x * UB;
    const int bh   = blockIdx.y;
    const int b0g  = bh * MROWS;
    const unsigned ep = (unsigned)layer * LAYER_EP;
    const uint32_t sfbase = smem_u32(sflag);

    // --- setup (all warps participate in loads; watcher idles in guarded parts) ---
    const float* Uc = U_raw + (size_t)layer * UNITS * NC;
    for (int i = tid; i < 128 * 6 * 32; i += GRU_THREADS) {
        int l2   = i & 31;
        int nt   = (i >> 5) % 6;
        int k8   = i / (6 * 32);
        int ltig = l2 & 3, lgid = l2 >> 2;
        int col  = nt * 8 + lgid;
        int gate = col >> 4, uu = col & 15;
        size_t cofs = (size_t)gate * UNITS + u0 + uu;
        float v0 = tf32r(Uc[(size_t)(8 * k8 + ltig) * NC + cofs]);
        float v1 = tf32r(Uc[(size_t)(8 * k8 + ltig + 4) * NC + cofs]);
        Up2[i] = make_float2(v0, v1);
    }
    if (tid < CCOLS) {
        int gate = tid >> 4, uu = tid & 15;
        sbias[tid] = bias1[gate * UNITS + u0 + uu];
    }
    if (tid < UGRP) sflag[tid] = 0u;

    // epilogue cell ownership (compute threads only): pb = tid>>2, inverse perm mlog
    const int pb   = tid >> 2;
    const int eb   = b0g + pb;
    const int eu4  = (tid & 3) * 4;
    const int mlog = ((pb >> 5) << 5) + ((pb >> 2) & 7) + ((pb & 3) << 3);

    float hreg[4];
    if (tid < 256) {
        const float* src = h0 + ((size_t)eb * UNITS + u0 + eu4) * LAYERS + layer;
        hreg[0] = src[0]; hreg[1] = src[3]; hreg[2] = src[6]; hreg[3] = src[9];
        g_hT[0][u0 + eu4 + 0][eb] = tf32r(hreg[0]);
        g_hT[0][u0 + eu4 + 1][eb] = tf32r(hreg[1]);
        g_hT[0][u0 + eu4 + 2][eb] = tf32r(hreg[2]);
        g_hT[0][u0 + eu4 + 3][eb] = tf32r(hreg[3]);
    }
    __syncthreads();                       // last full-CTA barrier before divergence
    if (tid < 256) red_release(&g_flag[bh][blockIdx.x]);

    if (wid == 8) {
        // ---- watcher warp: mirror g_flag[bh][0..63] into sflag with rel/acq chain ----
        const unsigned fin = ep + (unsigned)ARR * TSEQ;   // last level consumers wait on
        const unsigned* f0 = &g_flag[bh][lane];
        const unsigned* f1 = &g_flag[bh][lane + 32];
        uint32_t s0 = sfbase + lane * 4, s1 = sfbase + (lane + 32) * 4;
        unsigned c0 = 0, c1 = 0;
        while (c0 < fin || c1 < fin) {
            unsigned v0 = ldacq_gpu(f0);
            if (v0 != c0) { sts_rel(s0, v0); c0 = v0; }
            unsigned v1 = ldacq_gpu(f1);
            if (v1 != c1) { sts_rel(s1, v1); c1 = v1; }
        }
        return;
    }

    // ---- compute warps (tid < 256) ----
    const int wm   = wid & 1, wk = wid >> 1;
    const int mb   = wm * 32;
    const int kq   = wk * 32;
    const int GQ   = wk * 16;
    const int cph  = wm * 32 + 4 * gid;

#define PREFETCH(slot, step) do {                                              \
        const float* rp = hTp + (size_t)((kq + (step)) * 8 + tig) * BATCH + cph; \
        float4 v0 = *(const float4*)(rp);                                      \
        float4 v1 = *(const float4*)(rp + 4 * BATCH);                          \
        ar[slot][0][0] = __float_as_uint(v0.x);                                \
        ar[slot][0][1] = __float_as_uint(v0.y);                                \
        ar[slot][1][0] = __float_as_uint(v0.z);                                \
        ar[slot][1][1] = __float_as_uint(v0.w);                                \
        ar[slot][0][2] = __float_as_uint(v1.x);                                \
        ar[slot][0][3] = __float_as_uint(v1.y);                                \
        ar[slot][1][2] = __float_as_uint(v1.z);                                \
        ar[slot][1][3] = __float_as_uint(v1.w);                                \
    } while (0)

    for (int t = 0; t < TSEQ; t++) {
        const int rb = t & 1;
        const float* hTp = &g_hT[rb][0][b0g];
        const unsigned wt = ep + (unsigned)ARR * (t + 1);

        const float* xwrow = g_xw + ((size_t)t * BATCH + eb) * NC + u0 + eu4;
        float4 xz4 = *(const float4*)(xwrow);
        float4 xr4 = *(const float4*)(xwrow + UNITS);
        float4 xh4 = *(const float4*)(xwrow + 2 * UNITS);

        float acc[2][6][4];
#pragma unroll
        for (int i = 0; i < 2; i++)
#pragma unroll
            for (int j = 0; j < 6; j++)
#pragma unroll
                for (int q = 0; q < 4; q++) acc[i][j][q] = 0.f;

        unsigned ar[8][2][4];
        wait_sflag(sfbase + GQ * 4, wt);
        PREFETCH(0, 0);
        PREFETCH(1, 1);
        wait_sflag(sfbase + (GQ + 1) * 4, wt);
        PREFETCH(2, 2);
        PREFETCH(3, 3);

#pragma unroll
        for (int u = 0; u < 32; u++) {
            if (u < 28) {
                if ((u & 1) == 0) wait_sflag(sfbase + ((kq + u + 4) >> 1) * 4, wt);
                PREFETCH((u + 4) & 7, u + 4);
            }
            const int gk8 = kq + u;
            unsigned bfr[6][2];
#pragma unroll
            for (int nt = 0; nt < 6; nt++) {
                float2 bq = Up2[(gk8 * 6 + nt) * 32 + lane];
                bfr[nt][0] = __float_as_uint(bq.x);
                bfr[nt][1] = __float_as_uint(bq.y);
            }
#pragma unroll
            for (int mt = 0; mt < 2; mt++)
#pragma unroll
                for (int nt = 0; nt < 6; nt++)
                    mma_tf32(acc[mt][nt], ar[u & 7][mt], bfr[nt]);
        }
        NB_SYNC();

        // 2 parallel merge passes (logical m rows)
        float* HUd = (wk & 2) ? HUB : HUA;
        if ((wk & 1) == 0) {
#pragma unroll
            for (int mt = 0; mt < 2; mt++)
#pragma unroll
                for (int nt = 0; nt < 6; nt++) {
                    int m = mb + mt * 16 + gid;
                    int n = nt * 8 + 2 * tig;
                    HUd[m * HUSTR + n]           = acc[mt][nt][0];
                    HUd[m * HUSTR + n + 1]       = acc[mt][nt][1];
                    HUd[(m + 8) * HUSTR + n]     = acc[mt][nt][2];
                    HUd[(m + 8) * HUSTR + n + 1] = acc[mt][nt][3];
                }
        }
        NB_SYNC();
        if ((wk & 1) == 1) {
#pragma unroll
            for (int mt = 0; mt < 2; mt++)
#pragma unroll
                for (int nt = 0; nt < 6; nt++) {
                    int m = mb + mt * 16 + gid;
                    int n = nt * 8 + 2 * tig;
                    HUd[m * HUSTR + n]           += acc[mt][nt][0];
                    HUd[m * HUSTR + n + 1]       += acc[mt][nt][1];
                    HUd[(m + 8) * HUSTR + n]     += acc[mt][nt][2];
                    HUd[(m + 8) * HUSTR + n + 1] += acc[mt][nt][3];
                }
        }
        NB_SYNC();

        // gate epilogue (HU indexed by logical m via inverse permutation)
        const int wb = 1 - rb;
        float hn4[4];
        const float xz[4] = {xz4.x, xz4.y, xz4.z, xz4.w};
        const float xr[4] = {xr4.x, xr4.y, xr4.z, xr4.w};
        const float xh[4] = {xh4.x, xh4.y, xh4.z, xh4.w};
#pragma unroll
        for (int j = 0; j < 4; j++) {
            int uu = eu4 + j;
            float hz = HUA[mlog * HUSTR + uu]          + HUB[mlog * HUSTR + uu]          + sbias[uu];
            float hr = HUA[mlog * HUSTR + UB + uu]     + HUB[mlog * HUSTR + UB + uu]     + sbias[UB + uu];
            float hh = HUA[mlog * HUSTR + 2 * UB + uu] + HUB[mlog * HUSTR + 2 * UB + uu] + sbias[2 * UB + uu];
            float z    = 1.f / (1.f + __expf(-(xz[j] + hz)));
            float rg   = 1.f / (1.f + __expf(-(xr[j] + hr)));
            float hhat = tanhf(xh[j] + rg * hh);
            float hn   = z * hreg[j] + (1.f - z) * hhat;
            hreg[j] = hn;
            hn4[j] = hn;
            g_hT[wb][u0 + uu][eb] = tf32r(hn);
        }
        size_t yi = ((size_t)eb * TSEQ + t) * UNITS + u0 + eu4;
        if (is_last) {
            *(float4*)(yout + yi) = make_float4(hn4[0], hn4[1], hn4[2], hn4[3]);
        } else {
            *(float4*)(g_x + yi) =
                make_float4(tf32r(hn4[0]), tf32r(hn4[1]), tf32r(hn4[2]), tf32r(hn4[3]));
        }
        red_release(&g_flag[bh][blockIdx.x]);
    }
#undef PREFETCH

    // final states
    {
        float* d = out_states + ((size_t)eb * UNITS + u0 + eu4) * LAYERS + layer;
        d[0] = hreg[0]; d[3] = hreg[1]; d[6] = hreg[2]; d[9] = hreg[3];
    }
}

// ---------------- host launcher ----------------
extern "C" void kernel_launch(void* const* d_in, const int* in_sizes, int n_in,
                              void* d_out, int out_size) {
    (void)in_sizes; (void)n_in; (void)out_size;
    const float* x_in = (const float*)d_in[0];
    const float* h0   = (const float*)d_in[1];
    const float* W    = (const float*)d_in[2];
    const float* U    = (const float*)d_in[3];
    const float* b    = (const float*)d_in[4];
    float* out        = (float*)d_out;
    float* out_states = out + (size_t)MXW * UNITS;

    static float* g_x_ptr = nullptr;
    static float* g_Wc_ptr = nullptr;
    if (!g_x_ptr)  cudaGetSymbolAddress((void**)&g_x_ptr, g_x);
    if (!g_Wc_ptr) cudaGetSymbolAddress((void**)&g_Wc_ptr, g_Wc);

    cudaFuncSetAttribute(gru_layer_kernel,
                         cudaFuncAttributeMaxDynamicSharedMemorySize, GRU_SMEM);
    cudaFuncSetAttribute(gemm_xw_kernel,
                         cudaFuncAttributeMaxDynamicSharedMemorySize, XW_SMEM);

    cvt_weights_kernel<<<4096, 256>>>(W);   // also resets flags each replay
    cvt_input_kernel<<<8192, 256>>>(x_in);

    for (int l = 0; l < LAYERS; l++) {
        gemm_xw_kernel<<<dim3(NC / BN, MXW / BM), 256, XW_SMEM>>>(
            g_x_ptr, g_Wc_ptr + (size_t)l * UNITS * NC, b + (size_t)l * 2 * NC);
        gru_layer_kernel<<<dim3(UGRP, 2), GRU_THREADS, GRU_SMEM>>>(
            l, h0, U, b + (size_t)l * 2 * NC + NC, out, out_states, l == LAYERS - 1);
    }
}